// round 1
// baseline (speedup 1.0000x reference)
#include <cuda_runtime.h>
#include <cuda_bf16.h>
#include <math.h>

// Problem constants
#define B_SZ 4
#define SEQ 1024
#define EMB 1024
#define NH 16
#define HD 64
#define QKV3 (3 * NH * HD)   // 3072
#define ROWS (B_SZ * SEQ)    // 4096

// Scratch (device globals: allocation-free rule)
__device__ float g_qkv[(size_t)ROWS * QKV3];   // [4096, 3072]  (K | Q | V)
__device__ float g_att[(size_t)ROWS * EMB];    // [4096, 1024]

// ----------------------------------------------------------------------------
// GEMM: C[M,N] = A[M,K] @ B[K,N] + bias  (128x128x16 tile, 8x8 microtile)
// ----------------------------------------------------------------------------
#define BM 128
#define BN 128
#define BK 16
__global__ void __launch_bounds__(256, 2) sgemm_bias(
    const float* __restrict__ A, const float* __restrict__ B,
    const float* __restrict__ bias, float* __restrict__ C,
    int M, int N, int K)
{
    __shared__ float As[BK][BM + 4];   // transposed, padded (store 2-way ok, reads bcast)
    __shared__ float Bs[BK][BN];

    const int tid = threadIdx.x;
    const int tx = tid & 15;          // 0..15
    const int ty = tid >> 4;          // 0..15
    const int m0 = blockIdx.y * BM;
    const int n0 = blockIdx.x * BN;

    float acc[8][8];
#pragma unroll
    for (int i = 0; i < 8; i++)
#pragma unroll
        for (int j = 0; j < 8; j++) acc[i][j] = 0.f;

    for (int k0 = 0; k0 < K; k0 += BK) {
        // Load A tile (128 rows x 16 k) -> As[k][row]
#pragma unroll
        for (int i = 0; i < 2; i++) {
            int lin = tid + i * 256;          // float4 idx 0..511
            int row = lin >> 2;               // 0..127
            int kc  = (lin & 3) << 2;         // 0,4,8,12
            float4 v = *(const float4*)(A + (size_t)(m0 + row) * K + k0 + kc);
            As[kc + 0][row] = v.x;
            As[kc + 1][row] = v.y;
            As[kc + 2][row] = v.z;
            As[kc + 3][row] = v.w;
        }
        // Load B tile (16 rows x 128 cols)
#pragma unroll
        for (int i = 0; i < 2; i++) {
            int lin = tid + i * 256;          // float4 idx 0..511
            int row = lin >> 5;               // 0..15
            int cc  = (lin & 31) << 2;        // 0..124
            *(float4*)&Bs[row][cc] =
                *(const float4*)(B + (size_t)(k0 + row) * N + n0 + cc);
        }
        __syncthreads();

#pragma unroll
        for (int k = 0; k < BK; k++) {
            float a[8], b[8];
            float4 a0 = *(float4*)&As[k][ty * 8];
            float4 a1 = *(float4*)&As[k][ty * 8 + 4];
            float4 b0 = *(float4*)&Bs[k][tx * 8];
            float4 b1 = *(float4*)&Bs[k][tx * 8 + 4];
            a[0]=a0.x; a[1]=a0.y; a[2]=a0.z; a[3]=a0.w;
            a[4]=a1.x; a[5]=a1.y; a[6]=a1.z; a[7]=a1.w;
            b[0]=b0.x; b[1]=b0.y; b[2]=b0.z; b[3]=b0.w;
            b[4]=b1.x; b[5]=b1.y; b[6]=b1.z; b[7]=b1.w;
#pragma unroll
            for (int i = 0; i < 8; i++)
#pragma unroll
                for (int j = 0; j < 8; j++)
                    acc[i][j] = fmaf(a[i], b[j], acc[i][j]);
        }
        __syncthreads();
    }

    // Epilogue: += bias, write C
    float4 bia0 = *(const float4*)(bias + n0 + tx * 8);
    float4 bia1 = *(const float4*)(bias + n0 + tx * 8 + 4);
#pragma unroll
    for (int i = 0; i < 8; i++) {
        float* crow = C + (size_t)(m0 + ty * 8 + i) * N + n0 + tx * 8;
        float4 o0 = make_float4(acc[i][0] + bia0.x, acc[i][1] + bia0.y,
                                acc[i][2] + bia0.z, acc[i][3] + bia0.w);
        float4 o1 = make_float4(acc[i][4] + bia1.x, acc[i][5] + bia1.y,
                                acc[i][6] + bia1.z, acc[i][7] + bia1.w);
        *(float4*)(crow)     = o0;
        *(float4*)(crow + 4) = o1;
    }
}

// ----------------------------------------------------------------------------
// Flash attention: one block per (b, h, 64-row q tile). 256 threads.
// Thread t: row r = t/4, hd-col group c0 = (t%4)*16 (16 output cols).
// Smem swizzles (all preserve 16B alignment; deltas are multiples of 4 words):
//   Q/K tiles:  col ^ 4*((row>>4) ^ (row&7))   -> conflict-free for both the
//               per-warp-row Q reads and the c0-strided K reads
//   V tile:     col ^ 4*((col>>4)&3)           -> 4 distinct banks across c0 groups
//   P tile:     col ^ 4*(row&7)                -> conflict-free row-strided reads
// ----------------------------------------------------------------------------
__device__ __forceinline__ int swQK(int row, int col) {
    return col ^ ((((row >> 4) ^ (row & 7)) & 7) << 2);
}
__device__ __forceinline__ int swV(int col) {
    return col ^ (((col >> 4) & 3) << 2);
}
__device__ __forceinline__ int swP(int row, int col) {
    return col ^ ((row & 7) << 2);
}

__global__ void __launch_bounds__(256, 3) attn_kernel(
    const float* __restrict__ qkv, float* __restrict__ outb)
{
    __shared__ float Qs[64 * 64];
    __shared__ float Ks[64 * 64];
    __shared__ float Vs[64 * 64];
    __shared__ float Ps[64 * 64];

    const int tid = threadIdx.x;
    const int bh = blockIdx.y;
    const int b = bh >> 4, h = bh & 15;
    const int qbase = blockIdx.x * 64;
    const int r  = tid >> 2;           // 0..63
    const int c0 = (tid & 3) << 4;     // 0,16,32,48

    // qkv row layout: [K(0..1023) | Q(1024..2047) | V(2048..3071)], head h at h*64
    const float* base = qkv + (size_t)b * SEQ * QKV3 + (size_t)h * HD;

    // Load Q tile (swizzled)
#pragma unroll
    for (int i = 0; i < 4; i++) {
        int lin = tid + i * 256;           // float4 idx 0..1023
        int row = lin >> 4;
        int cc  = (lin & 15) << 2;
        float4 v = *(const float4*)(base + (size_t)(qbase + row) * QKV3 + 1024 + cc);
        *(float4*)&Qs[row * 64 + swQK(row, cc)] = v;
    }

    float m = -1e30f, l = 0.f;
    float O[16];
#pragma unroll
    for (int j = 0; j < 16; j++) O[j] = 0.f;

    const float scale = 0.125f;   // 1/sqrt(64)

    for (int kt = 0; kt < 16; kt++) {
        __syncthreads();   // protect K/V/P reuse from previous iteration
        const int kbase = kt * 64;
#pragma unroll
        for (int i = 0; i < 4; i++) {
            int lin = tid + i * 256;
            int row = lin >> 4;
            int cc  = (lin & 15) << 2;
            const float* grow = base + (size_t)(kbase + row) * QKV3;
            float4 kv = *(const float4*)(grow + cc);          // K chunk
            float4 vv = *(const float4*)(grow + 2048 + cc);   // V chunk
            *(float4*)&Ks[row * 64 + swQK(row, cc)] = kv;
            *(float4*)&Vs[row * 64 + swV(cc)]       = vv;
        }
        __syncthreads();

        // Scores: s[j] = Q[r,:] . K[c0+j,:]
        float s[16];
#pragma unroll
        for (int j = 0; j < 16; j++) s[j] = 0.f;
#pragma unroll
        for (int d = 0; d < 64; d += 4) {
            float4 q = *(float4*)&Qs[r * 64 + swQK(r, d)];
#pragma unroll
            for (int j = 0; j < 16; j++) {
                int krow = c0 + j;
                float4 kv = *(float4*)&Ks[krow * 64 + swQK(krow, d)];
                s[j] += q.x * kv.x + q.y * kv.y + q.z * kv.z + q.w * kv.w;
            }
        }

        // Online softmax (4 lanes per row -> quad reduce via shfl_xor 1,2)
        float tmax = -1e30f;
#pragma unroll
        for (int j = 0; j < 16; j++) { s[j] *= scale; tmax = fmaxf(tmax, s[j]); }
        tmax = fmaxf(tmax, __shfl_xor_sync(0xffffffffu, tmax, 1));
        tmax = fmaxf(tmax, __shfl_xor_sync(0xffffffffu, tmax, 2));
        float mnew  = fmaxf(m, tmax);
        float alpha = __expf(m - mnew);
        float psum = 0.f;
#pragma unroll
        for (int j = 0; j < 16; j++) {
            float p = __expf(s[j] - mnew);
            Ps[r * 64 + swP(r, c0 + j)] = p;
            psum += p;
        }
        psum += __shfl_xor_sync(0xffffffffu, psum, 1);
        psum += __shfl_xor_sync(0xffffffffu, psum, 2);
        l = l * alpha + psum;
        m = mnew;
#pragma unroll
        for (int j = 0; j < 16; j++) O[j] *= alpha;
        __syncthreads();   // P fully written before cross-thread reads

        // O[r, c0+j] += sum_k P[r,k] * V[k, c0+j]
#pragma unroll
        for (int k = 0; k < 64; k += 4) {
            float4 p4 = *(float4*)&Ps[r * 64 + swP(r, k)];
            float pk[4] = {p4.x, p4.y, p4.z, p4.w};
#pragma unroll
            for (int kk = 0; kk < 4; kk++) {
                float p = pk[kk];
#pragma unroll
                for (int j = 0; j < 16; j += 4) {
                    float4 v = *(float4*)&Vs[(k + kk) * 64 + swV(c0 + j)];
                    O[j + 0] = fmaf(p, v.x, O[j + 0]);
                    O[j + 1] = fmaf(p, v.y, O[j + 1]);
                    O[j + 2] = fmaf(p, v.z, O[j + 2]);
                    O[j + 3] = fmaf(p, v.w, O[j + 3]);
                }
            }
        }
    }

    // Finalize and store: out[b*1024+qbase+r, h*64 + c0 + j]
    float inv = 1.f / l;
    float* orow = outb + (size_t)(b * SEQ + qbase + r) * EMB + h * HD + c0;
#pragma unroll
    for (int j = 0; j < 16; j += 4) {
        float4 v = make_float4(O[j] * inv, O[j + 1] * inv, O[j + 2] * inv, O[j + 3] * inv);
        *(float4*)(orow + j) = v;
    }
}

// ----------------------------------------------------------------------------
// Launch
// ----------------------------------------------------------------------------
extern "C" void kernel_launch(void* const* d_in, const int* in_sizes, int n_in,
                              void* d_out, int out_size)
{
    const float* x     = (const float*)d_in[0];  // [4,1024,1024]
    const float* W_qkv = (const float*)d_in[1];  // [1024,3072]
    const float* b_qkv = (const float*)d_in[2];  // [3072]
    const float* W_out = (const float*)d_in[3];  // [1024,1024]
    const float* b_out = (const float*)d_in[4];  // [1024]
    float* out = (float*)d_out;                  // [4,1024,1024]

    void* p_qkv = nullptr;
    void* p_att = nullptr;
    cudaGetSymbolAddress(&p_qkv, g_qkv);
    cudaGetSymbolAddress(&p_att, g_att);
    float* qkvbuf = (float*)p_qkv;
    float* attbuf = (float*)p_att;

    // 1) QKV projection: [4096,1024] @ [1024,3072] + b_qkv
    {
        dim3 grid(QKV3 / BN, ROWS / BM);   // (24, 32)
        sgemm_bias<<<grid, 256>>>(x, W_qkv, b_qkv, qkvbuf, ROWS, QKV3, EMB);
    }
    // 2) Attention (flash, per (qtile, b*16+h))
    {
        dim3 grid(SEQ / 64, B_SZ * NH);    // (16, 64)
        attn_kernel<<<grid, 256>>>(qkvbuf, attbuf);
    }
    // 3) Output projection: [4096,1024] @ [1024,1024] + b_out
    {
        dim3 grid(EMB / BN, ROWS / BM);    // (8, 32)
        sgemm_bias<<<grid, 256>>>(attbuf, W_out, b_out, out, ROWS, EMB, EMB);
    }
}

// round 17
// speedup vs baseline: 2.2961x; 2.2961x over previous
#include <cuda_runtime.h>
#include <cuda_bf16.h>
#include <math.h>
#include <stdint.h>

// Problem constants
#define B_SZ 4
#define SEQ 1024
#define EMB 1024
#define NH 16
#define HD 64
#define QKV3 (3 * NH * HD)   // 3072
#define ROWS (B_SZ * SEQ)    // 4096

// ---------------------------------------------------------------------------
// Scratch (device globals: allocation-free rule)
// ---------------------------------------------------------------------------
__device__ float g_qkv[(size_t)ROWS * QKV3];   // [4096, 3072]  (K | Q | V)
__device__ float g_att[(size_t)ROWS * EMB];    // [4096, 1024]
// bf16 split copies
__device__ __nv_bfloat16 g_xh[(size_t)ROWS * EMB];
__device__ __nv_bfloat16 g_xl[(size_t)ROWS * EMB];
__device__ __nv_bfloat16 g_ah[(size_t)ROWS * EMB];
__device__ __nv_bfloat16 g_al[(size_t)ROWS * EMB];
__device__ __nv_bfloat16 g_wqh[(size_t)QKV3 * EMB];  // W_qkv^T [3072,1024]
__device__ __nv_bfloat16 g_wql[(size_t)QKV3 * EMB];
__device__ __nv_bfloat16 g_woh[(size_t)EMB * EMB];   // W_out^T [1024,1024]
__device__ __nv_bfloat16 g_wol[(size_t)EMB * EMB];

// ---------------------------------------------------------------------------
// Split fp32 -> bf16 hi/lo (elementwise, vectorized by 4)
// ---------------------------------------------------------------------------
__global__ void split_f32(const float4* __restrict__ in,
                          uint2* __restrict__ hi, uint2* __restrict__ lo, int n4)
{
    int i = blockIdx.x * 256 + threadIdx.x;
    if (i >= n4) return;
    float4 v = in[i];
    __nv_bfloat16 h[4], l[4];
    float vv[4] = {v.x, v.y, v.z, v.w};
#pragma unroll
    for (int t = 0; t < 4; t++) {
        h[t] = __float2bfloat16(vv[t]);
        l[t] = __float2bfloat16(vv[t] - __bfloat162float(h[t]));
    }
    hi[i] = *(uint2*)h;
    lo[i] = *(uint2*)l;
}

// ---------------------------------------------------------------------------
// Split + transpose: W [K,N] fp32 row-major -> hiT/loT [N,K] bf16 row-major
// ---------------------------------------------------------------------------
__global__ void transpose_split(const float* __restrict__ W,
                                __nv_bfloat16* __restrict__ hiT,
                                __nv_bfloat16* __restrict__ loT, int K, int N)
{
    __shared__ float t[32][33];
    const int n0 = blockIdx.x * 32, k0 = blockIdx.y * 32;
    const int tx = threadIdx.x, ty = threadIdx.y;  // (32, 8)
#pragma unroll
    for (int r = ty; r < 32; r += 8)
        t[r][tx] = W[(size_t)(k0 + r) * N + n0 + tx];
    __syncthreads();
#pragma unroll
    for (int r = ty; r < 32; r += 8) {
        float v = t[tx][r];  // = W[k0+tx][n0+r]
        __nv_bfloat16 h = __float2bfloat16(v);
        __nv_bfloat16 l = __float2bfloat16(v - __bfloat162float(h));
        hiT[(size_t)(n0 + r) * K + k0 + tx] = h;
        loT[(size_t)(n0 + r) * K + k0 + tx] = l;
    }
}

// ---------------------------------------------------------------------------
// mma.sync bf16 split GEMM: C[M,N] = (Ah+Al)[M,K] @ (Bh+Bl)T[N,K]^T + bias
// m16n8k16 HMMA, fp32 register accumulators. CTA tile 128x128, 8 warps (4x2),
// warp tile 32x64. K staged in 64-element chunks; smem pitch 36 words makes
// every fragment load (addr = g*36 + t mod 32 = g*4+t) bank-conflict-free.
// Splits: D = Ah*Bh + Ah*Bl + Al*Bh (Al*Bl dropped, ~2^-16 rel).
// ---------------------------------------------------------------------------
#define GP 36                        // smem row pitch in 32-bit words
#define TILE_WORDS (128 * GP)        // words per staged array
#define GEMM_SMEM_BYTES (4 * TILE_WORDS * 4)   // 73728

__device__ __forceinline__ void mma16816(float* d, const uint32_t* a, const uint32_t* b) {
    asm volatile(
        "mma.sync.aligned.m16n8k16.row.col.f32.bf16.bf16.f32 "
        "{%0,%1,%2,%3}, {%4,%5,%6,%7}, {%8,%9}, {%0,%1,%2,%3};"
        : "+f"(d[0]), "+f"(d[1]), "+f"(d[2]), "+f"(d[3])
        : "r"(a[0]), "r"(a[1]), "r"(a[2]), "r"(a[3]), "r"(b[0]), "r"(b[1]));
}

__global__ void __launch_bounds__(256) mma_gemm_bias(
    const __nv_bfloat16* __restrict__ Ah, const __nv_bfloat16* __restrict__ Al,
    const __nv_bfloat16* __restrict__ BhT, const __nv_bfloat16* __restrict__ BlT,
    const float* __restrict__ bias, float* __restrict__ C,
    int M, int N, int K)
{
    extern __shared__ uint32_t sm[];
    uint32_t* sAh = sm;
    uint32_t* sAl = sm + TILE_WORDS;
    uint32_t* sBh = sm + 2 * TILE_WORDS;
    uint32_t* sBl = sm + 3 * TILE_WORDS;

    const int tid = threadIdx.x;
    const int wid = tid >> 5, lane = tid & 31;
    const int g = lane >> 2, t = lane & 3;      // mma group / pair index
    const int wm = wid & 3, wn = wid >> 2;      // 4x2 warp grid
    const int m0 = blockIdx.y * 128, n0 = blockIdx.x * 128;

    float d[2][8][4];
#pragma unroll
    for (int i = 0; i < 2; i++)
#pragma unroll
        for (int j = 0; j < 8; j++)
#pragma unroll
            for (int c = 0; c < 4; c++) d[i][j][c] = 0.f;

    for (int kc = 0; kc < K; kc += 64) {
        if (kc) __syncthreads();   // previous chunk fully consumed
        // Stage chunk: 128 rows x 64 bf16 per array, uint4 (8 bf16) per store
#pragma unroll
        for (int i = 0; i < 4; i++) {
            int lin = tid + (i << 8);
            int row = lin >> 3;          // 0..127
            int q   = lin & 7;           // uint4 index within row
            uint32_t wo = row * GP + (q << 2);
            *(uint4*)(sAh + wo) = *((const uint4*)(Ah  + (size_t)(m0 + row) * K + kc) + q);
            *(uint4*)(sAl + wo) = *((const uint4*)(Al  + (size_t)(m0 + row) * K + kc) + q);
            *(uint4*)(sBh + wo) = *((const uint4*)(BhT + (size_t)(n0 + row) * K + kc) + q);
            *(uint4*)(sBl + wo) = *((const uint4*)(BlT + (size_t)(n0 + row) * K + kc) + q);
        }
        __syncthreads();

#pragma unroll
        for (int ks = 0; ks < 4; ks++) {     // 4 x k16 per chunk
            const int kw = ks << 3;          // word offset of this k16
            uint32_t ah[2][4], al[2][4], bh[8][2], bl[8][2];
#pragma unroll
            for (int mt = 0; mt < 2; mt++) {
                int rb = wm * 32 + mt * 16;
                uint32_t o0 = (rb + g) * GP + kw + t;
                uint32_t o1 = (rb + g + 8) * GP + kw + t;
                ah[mt][0] = sAh[o0];     ah[mt][1] = sAh[o1];
                ah[mt][2] = sAh[o0 + 4]; ah[mt][3] = sAh[o1 + 4];
                al[mt][0] = sAl[o0];     al[mt][1] = sAl[o1];
                al[mt][2] = sAl[o0 + 4]; al[mt][3] = sAl[o1 + 4];
            }
#pragma unroll
            for (int nt = 0; nt < 8; nt++) {
                int nb = wn * 64 + nt * 8;
                uint32_t o = (nb + g) * GP + kw + t;
                bh[nt][0] = sBh[o]; bh[nt][1] = sBh[o + 4];
                bl[nt][0] = sBl[o]; bl[nt][1] = sBl[o + 4];
            }
#pragma unroll
            for (int mt = 0; mt < 2; mt++)
#pragma unroll
                for (int nt = 0; nt < 8; nt++) {
                    mma16816(d[mt][nt], ah[mt], bh[nt]);
                    mma16816(d[mt][nt], ah[mt], bl[nt]);
                    mma16816(d[mt][nt], al[mt], bh[nt]);
                }
        }
    }

    // Epilogue: registers -> gmem with bias (c0,c1 -> row g; c2,c3 -> row g+8)
#pragma unroll
    for (int mt = 0; mt < 2; mt++) {
        int rowa = m0 + wm * 32 + mt * 16 + g;
#pragma unroll
        for (int nt = 0; nt < 8; nt++) {
            int col = n0 + wn * 64 + nt * 8 + 2 * t;
            float2 bb = *(const float2*)(bias + col);
            float2 v0 = make_float2(d[mt][nt][0] + bb.x, d[mt][nt][1] + bb.y);
            float2 v1 = make_float2(d[mt][nt][2] + bb.x, d[mt][nt][3] + bb.y);
            *(float2*)(C + (size_t)rowa * N + col)       = v0;
            *(float2*)(C + (size_t)(rowa + 8) * N + col) = v1;
        }
    }
}

// ----------------------------------------------------------------------------
// Flash attention, 4x4 microtile mapping (halves LDS traffic vs 1x16).
// Block = (b, h, 64-row q tile), 256 threads: thread t handles
// rows r0 = (t>>4)*4 .. +3 and cols c0 = (t&15)*4 .. +3.
// Swizzle: word col ^ (((row>>2)&7)<<2) -> every 8-lane phase of each .128
// access hits 8 distinct 16B banks.
// ----------------------------------------------------------------------------
__device__ __forceinline__ int swA(int row) { return ((row >> 2) & 7) << 2; }

__global__ void __launch_bounds__(256, 3) attn_kernel(
    const float* __restrict__ qkv, float* __restrict__ outb)
{
    __shared__ float Qs[64 * 64];
    __shared__ float Ks[64 * 64];
    __shared__ float Vs[64 * 64];
    __shared__ float Ps[64 * 64];

    const int tid = threadIdx.x;
    const int bh = blockIdx.y;
    const int b = bh >> 4, h = bh & 15;
    const int qbase = blockIdx.x * 64;
    const int rg = tid >> 4;           // 0..15
    const int cg = tid & 15;           // 0..15
    const int r0 = rg << 2;            // 4 rows per thread
    const int c0 = cg << 2;            // 4 cols per thread
    const int swr = swA(r0);           // constant for all 4 thread rows
    const int swc = swA(c0);           // constant for all 4 thread cols

    // qkv row layout: [K(0..1023) | Q(1024..2047) | V(2048..3071)], head h at h*64
    const float* base = qkv + (size_t)b * SEQ * QKV3 + (size_t)h * HD;

    // Load Q tile (swizzled)
#pragma unroll
    for (int i = 0; i < 4; i++) {
        int lin = tid + i * 256;           // float4 idx 0..1023
        int row = lin >> 4;
        int cc  = (lin & 15) << 2;
        float4 v = *(const float4*)(base + (size_t)(qbase + row) * QKV3 + 1024 + cc);
        *(float4*)&Qs[row * 64 + (cc ^ swA(row))] = v;
    }

    float m[4], l[4], O[4][4];
#pragma unroll
    for (int i = 0; i < 4; i++) {
        m[i] = -1e30f; l[i] = 0.f;
#pragma unroll
        for (int j = 0; j < 4; j++) O[i][j] = 0.f;
    }

    const float scale = 0.125f;   // 1/sqrt(64)

    for (int kt = 0; kt < 16; kt++) {
        __syncthreads();   // protect K/V/P reuse from previous iteration
        const int kbase = kt * 64;
#pragma unroll
        for (int i = 0; i < 4; i++) {
            int lin = tid + i * 256;
            int row = lin >> 4;
            int cc  = (lin & 15) << 2;
            const float* grow = base + (size_t)(kbase + row) * QKV3;
            float4 kv = *(const float4*)(grow + cc);          // K chunk
            float4 vv = *(const float4*)(grow + 2048 + cc);   // V chunk
            int sw = cc ^ swA(row);
            *(float4*)&Ks[row * 64 + sw] = kv;
            *(float4*)&Vs[row * 64 + sw] = vv;
        }
        __syncthreads();

        // Scores: s[i][j] = Q[r0+i,:] . K[c0+j,:]
        float s[4][4];
#pragma unroll
        for (int i = 0; i < 4; i++)
#pragma unroll
            for (int j = 0; j < 4; j++) s[i][j] = 0.f;
#pragma unroll
        for (int d = 0; d < 64; d += 4) {
            float4 q[4], k[4];
#pragma unroll
            for (int i = 0; i < 4; i++) q[i] = *(float4*)&Qs[(r0 + i) * 64 + (d ^ swr)];
#pragma unroll
            for (int j = 0; j < 4; j++) k[j] = *(float4*)&Ks[(c0 + j) * 64 + (d ^ swc)];
#pragma unroll
            for (int i = 0; i < 4; i++)
#pragma unroll
                for (int j = 0; j < 4; j++)
                    s[i][j] += q[i].x * k[j].x + q[i].y * k[j].y
                             + q[i].z * k[j].z + q[i].w * k[j].w;
        }

        // Online softmax: row reduction across the 16 cg lanes (xor 1,2,4,8)
#pragma unroll
        for (int i = 0; i < 4; i++) {
            float tmax = -1e30f;
#pragma unroll
            for (int j = 0; j < 4; j++) { s[i][j] *= scale; tmax = fmaxf(tmax, s[i][j]); }
            tmax = fmaxf(tmax, __shfl_xor_sync(0xffffffffu, tmax, 1));
            tmax = fmaxf(tmax, __shfl_xor_sync(0xffffffffu, tmax, 2));
            tmax = fmaxf(tmax, __shfl_xor_sync(0xffffffffu, tmax, 4));
            tmax = fmaxf(tmax, __shfl_xor_sync(0xffffffffu, tmax, 8));
            float mnew  = fmaxf(m[i], tmax);
            float alpha = __expf(m[i] - mnew);
            float p0 = __expf(s[i][0] - mnew);
            float p1 = __expf(s[i][1] - mnew);
            float p2 = __expf(s[i][2] - mnew);
            float p3 = __expf(s[i][3] - mnew);
            *(float4*)&Ps[(r0 + i) * 64 + (c0 ^ swr)] = make_float4(p0, p1, p2, p3);
            float psum = p0 + p1 + p2 + p3;
            psum += __shfl_xor_sync(0xffffffffu, psum, 1);
            psum += __shfl_xor_sync(0xffffffffu, psum, 2);
            psum += __shfl_xor_sync(0xffffffffu, psum, 4);
            psum += __shfl_xor_sync(0xffffffffu, psum, 8);
            l[i] = l[i] * alpha + psum;
            m[i] = mnew;
#pragma unroll
            for (int j = 0; j < 4; j++) O[i][j] *= alpha;
        }
        __syncthreads();   // P fully written before cross-thread reads

        // O[i][j] += sum_k P[r0+i,k] * V[k, c0+j]
#pragma unroll
        for (int kb = 0; kb < 64; kb += 4) {
            float4 p[4];
#pragma unroll
            for (int i = 0; i < 4; i++) p[i] = *(float4*)&Ps[(r0 + i) * 64 + (kb ^ swr)];
#pragma unroll
            for (int kk = 0; kk < 4; kk++) {
                float4 vv = *(float4*)&Vs[(kb + kk) * 64 + (c0 ^ swA(kb + kk))];
                float pi[4] = {kk == 0 ? p[0].x : kk == 1 ? p[0].y : kk == 2 ? p[0].z : p[0].w,
                               kk == 0 ? p[1].x : kk == 1 ? p[1].y : kk == 2 ? p[1].z : p[1].w,
                               kk == 0 ? p[2].x : kk == 1 ? p[2].y : kk == 2 ? p[2].z : p[2].w,
                               kk == 0 ? p[3].x : kk == 1 ? p[3].y : kk == 2 ? p[3].z : p[3].w};
#pragma unroll
                for (int i = 0; i < 4; i++) {
                    O[i][0] = fmaf(pi[i], vv.x, O[i][0]);
                    O[i][1] = fmaf(pi[i], vv.y, O[i][1]);
                    O[i][2] = fmaf(pi[i], vv.z, O[i][2]);
                    O[i][3] = fmaf(pi[i], vv.w, O[i][3]);
                }
            }
        }
    }

    // Finalize and store: out[b*1024+qbase+r0+i, h*64 + c0 + j]
#pragma unroll
    for (int i = 0; i < 4; i++) {
        float inv = 1.f / l[i];
        float* orow = outb + (size_t)(b * SEQ + qbase + r0 + i) * EMB + h * HD + c0;
        *(float4*)orow = make_float4(O[i][0] * inv, O[i][1] * inv,
                                     O[i][2] * inv, O[i][3] * inv);
    }
}

// ----------------------------------------------------------------------------
// Launch
// ----------------------------------------------------------------------------
extern "C" void kernel_launch(void* const* d_in, const int* in_sizes, int n_in,
                              void* d_out, int out_size)
{
    const float* x     = (const float*)d_in[0];
    const float* W_qkv = (const float*)d_in[1];
    const float* b_qkv = (const float*)d_in[2];
    const float* W_out = (const float*)d_in[3];
    const float* b_out = (const float*)d_in[4];
    float* out = (float*)d_out;

    void *p_qkv, *p_att, *p_xh, *p_xl, *p_ah, *p_al, *p_wqh, *p_wql, *p_woh, *p_wol;
    cudaGetSymbolAddress(&p_qkv, g_qkv);
    cudaGetSymbolAddress(&p_att, g_att);
    cudaGetSymbolAddress(&p_xh, g_xh);  cudaGetSymbolAddress(&p_xl, g_xl);
    cudaGetSymbolAddress(&p_ah, g_ah);  cudaGetSymbolAddress(&p_al, g_al);
    cudaGetSymbolAddress(&p_wqh, g_wqh); cudaGetSymbolAddress(&p_wql, g_wql);
    cudaGetSymbolAddress(&p_woh, g_woh); cudaGetSymbolAddress(&p_wol, g_wol);
    float* qkvbuf = (float*)p_qkv;
    float* attbuf = (float*)p_att;

    cudaFuncSetAttribute(mma_gemm_bias, cudaFuncAttributeMaxDynamicSharedMemorySize,
                         GEMM_SMEM_BYTES);

    const int n4 = ROWS * EMB / 4;   // 1M float4s

    // Prep: split x, split+transpose weights
    split_f32<<<n4 / 256, 256>>>((const float4*)x, (uint2*)p_xh, (uint2*)p_xl, n4);
    transpose_split<<<dim3(QKV3 / 32, EMB / 32), dim3(32, 8)>>>(
        W_qkv, (__nv_bfloat16*)p_wqh, (__nv_bfloat16*)p_wql, EMB, QKV3);
    transpose_split<<<dim3(EMB / 32, EMB / 32), dim3(32, 8)>>>(
        W_out, (__nv_bfloat16*)p_woh, (__nv_bfloat16*)p_wol, EMB, EMB);

    // 1) QKV projection (HMMA): [4096,1024] @ [1024,3072] + b_qkv
    mma_gemm_bias<<<dim3(QKV3 / 128, ROWS / 128), 256, GEMM_SMEM_BYTES>>>(
        (const __nv_bfloat16*)p_xh, (const __nv_bfloat16*)p_xl,
        (const __nv_bfloat16*)p_wqh, (const __nv_bfloat16*)p_wql,
        b_qkv, qkvbuf, ROWS, QKV3, EMB);

    // 2) Attention
    attn_kernel<<<dim3(SEQ / 64, B_SZ * NH), 256>>>(qkvbuf, attbuf);

    // 3) Split attention output, out projection (HMMA)
    split_f32<<<n4 / 256, 256>>>((const float4*)attbuf, (uint2*)p_ah, (uint2*)p_al, n4);
    mma_gemm_bias<<<dim3(EMB / 128, ROWS / 128), 256, GEMM_SMEM_BYTES>>>(
        (const __nv_bfloat16*)p_ah, (const __nv_bfloat16*)p_al,
        (const __nv_bfloat16*)p_woh, (const __nv_bfloat16*)p_wol,
        b_out, out, ROWS, EMB, EMB);
}